// round 4
// baseline (speedup 1.0000x reference)
#include <cuda_runtime.h>
#include <cuda_bf16.h>

// Problem constants
#define BB 8
#define NN 2048
#define FF 128
#define ROWS (BB*NN)            // 16384
#define ALPHA 0.2f

// ---------------- scratch (static device globals; no allocation) ----------
__device__ float    g_h[ROWS * FF];        // 8 MB  h = input @ W^T
__device__ float    g_src[ROWS];
__device__ float4   g_duv[ROWS];           // {dst, exp(dst), exp(0.2 dst), 0}
__device__ float    g_P[ROWS];             // exp(src)/Z'   (-1 flag = uniform row)
__device__ float    g_Q[ROWS];             // exp(0.2 src)/Z'
__device__ unsigned g_mask[ROWS * (NN/32)]; // 4 MB adjacency bitmask

// ---------------- packed fp32x2 helpers (FFMA2 — PTX only) ----------------
__device__ __forceinline__ unsigned long long pack2(float x, float y) {
    unsigned long long r;
    asm("mov.b64 %0, {%1, %2};" : "=l"(r) : "f"(x), "f"(y));
    return r;
}
__device__ __forceinline__ void fma2(unsigned long long& d,
                                     unsigned long long a,
                                     unsigned long long b) {
    asm("fma.rn.f32x2 %0, %1, %2, %0;" : "+l"(d) : "l"(a), "l"(b));
}
__device__ __forceinline__ float2 unpack2(unsigned long long v) {
    float2 r;
    asm("mov.b64 {%0, %1}, %2;" : "=f"(r.x), "=f"(r.y) : "l"(v));
    return r;
}

// ===========================================================================
// Kernel 1: h = input @ W^T.   h[r][c] = sum_k input[r][k] * W[c][k]
// ===========================================================================
__global__ __launch_bounds__(256) void k1_gemm(const float* __restrict__ input,
                                               const float* __restrict__ W) {
    __shared__ float shA[64][32];
    __shared__ float shBt[32][128];

    const int tid  = threadIdx.x;
    const int warp = tid >> 5;
    const int lane = tid & 31;
    const int row0 = blockIdx.x * 64;
    const int c0   = lane * 4;

    unsigned long long acc[8][2];
    #pragma unroll
    for (int r = 0; r < 8; ++r) { acc[r][0] = 0ull; acc[r][1] = 0ull; }

    for (int kc = 0; kc < 4; ++kc) {
        __syncthreads();
        for (int v = tid; v < 64*32; v += 256) {
            int r = v >> 5, k = v & 31;
            shA[r][k] = input[(size_t)(row0 + r) * FF + kc*32 + k];
        }
        for (int v = tid; v < 32*128; v += 256) {
            int c = v & 127, kk = v >> 7;
            shBt[kk][c] = W[(size_t)c * FF + kc*32 + kk];
        }
        __syncthreads();

        #pragma unroll 4
        for (int k = 0; k < 32; ++k) {
            ulonglong2 bv = *(const ulonglong2*)&shBt[k][c0];
            #pragma unroll
            for (int r = 0; r < 8; ++r) {
                float a = shA[warp*8 + r][k];
                unsigned long long ap = pack2(a, a);
                fma2(acc[r][0], ap, bv.x);
                fma2(acc[r][1], ap, bv.y);
            }
        }
    }

    #pragma unroll
    for (int r = 0; r < 8; ++r) {
        int row = row0 + warp*8 + r;
        float2 p0 = unpack2(acc[r][0]);
        float2 p1 = unpack2(acc[r][1]);
        float4 o = make_float4(p0.x, p0.y, p1.x, p1.y);
        *(float4*)&g_h[(size_t)row * FF + c0] = o;
    }
}

// ===========================================================================
// Kernel 1b: src/dst projections + per-node exp factors. One warp per row.
// ===========================================================================
__global__ __launch_bounds__(256) void k1b_proj(const float* __restrict__ a_src,
                                                const float* __restrict__ a_dst) {
    const int warp = threadIdx.x >> 5;
    const int lane = threadIdx.x & 31;
    const int row  = blockIdx.x * 8 + warp;
    const float* hr = g_h + (size_t)row * FF;
    float s1 = 0.f, s2 = 0.f;
    #pragma unroll
    for (int c = lane; c < FF; c += 32) {
        float hv = hr[c];
        s1 += hv * __ldg(&a_src[c]);
        s2 += hv * __ldg(&a_dst[c]);
    }
    #pragma unroll
    for (int off = 16; off; off >>= 1) {
        s1 += __shfl_xor_sync(0xffffffffu, s1, off);
        s2 += __shfl_xor_sync(0xffffffffu, s2, off);
    }
    if (lane == 0) {
        g_src[row] = s1;
        g_duv[row] = make_float4(s2, __expf(s2), __expf(ALPHA * s2), 0.f);
    }
}

// ===========================================================================
// Kernel 2: adj scan -> bitmask + factorized softmax normalizer.
// Z' = exp(src)*sum_{allowed,e>0} U_j + exp(0.2 src)*sum_{allowed,e<=0} V_j
// One warp per row. No exp in the inner loop; DRAM-bound on adj.
// ===========================================================================
__global__ __launch_bounds__(256) void k2_stats(const int* __restrict__ adj) {
    const int warp = threadIdx.x >> 5;
    const int lane = threadIdx.x & 31;
    const int row  = blockIdx.x * 8 + warp;
    const int b    = row >> 11;
    const int i    = row & (NN-1);

    const int*    arow = adj + ((size_t)b * NN + i) * NN;
    const float4* duvb = g_duv + b * NN;
    const float   srci = g_src[row];

    float su = 0.f, sv = 0.f;
    for (int w = 0; w < NN/32; ++w) {
        int    j  = w*32 + lane;
        int    av = arow[j];
        float4 d  = __ldg(&duvb[j]);
        bool allowed = av > 0;
        unsigned bal = __ballot_sync(0xffffffffu, allowed);
        if (lane == 0) g_mask[(size_t)row * (NN/32) + w] = bal;
        if (allowed) {
            if (srci + d.x > 0.f) su += d.y;   // e>0 branch: U_j
            else                  sv += d.z;   // e<=0 branch: V_j
        }
    }
    #pragma unroll
    for (int off = 16; off; off >>= 1) {
        su += __shfl_xor_sync(0xffffffffu, su, off);
        sv += __shfl_xor_sync(0xffffffffu, sv, off);
    }
    float eS  = __expf(srci);
    float eS2 = __expf(ALPHA * srci);
    float Z   = eS * su + eS2 * sv;
    if (lane == 0) {
        if (Z > 0.f) { g_P[row] = eS / Z;  g_Q[row] = eS2 / Z; }
        else         { g_P[row] = -1.f;    g_Q[row] = 0.f;     }  // uniform flag
    }
    if (!(Z > 0.f)) {      // isolated row: softmax over all-NEG_INF = uniform
        g_mask[(size_t)row * (NN/32) + lane]      = 0xffffffffu;
        g_mask[(size_t)row * (NN/32) + 32 + lane] = 0xffffffffu;
    }
}

// ===========================================================================
// Kernel 3: out = ELU( att @ h ). att never materialized; weights are
// mask * (e>0 ? P_i*U_j : Q_i*V_j) — zero MUFU in the hot path.
// Block: 128 threads, tile 32 rows x 128 feats, j in tiles of 32. Grid=512.
// Thread = (ig 0..7 -> 4 rows) x (fg 0..15 -> 8 feats).
// ===========================================================================
__global__ __launch_bounds__(128) void k3_agg(float* __restrict__ out) {
    __shared__ float              sh_h[32][128];   // 16 KB  h tile (j x f)
    __shared__ unsigned long long sh_wp[32][32];   //  8 KB  {w,w} (i x j)
    __shared__ float sh_P[32], sh_Q[32], sh_src[32];
    __shared__ float sh_dst[32], sh_U[32], sh_V[32];

    const int tid  = threadIdx.x;
    const int row0 = blockIdx.x * 32;
    const int b    = row0 >> 11;
    const int ib   = (tid >> 4) * 4;      // 4-row group base (0..28)
    const int f0   = (tid & 15) * 8;      // 8-feat group base
    const float rN = 1.0f / (float)NN;

    if (tid < 32) {
        sh_P[tid]   = g_P[row0 + tid];
        sh_Q[tid]   = g_Q[row0 + tid];
        sh_src[tid] = g_src[row0 + tid];
    }

    unsigned long long acc[4][4];
    #pragma unroll
    for (int r = 0; r < 4; ++r)
        #pragma unroll
        for (int p = 0; p < 4; ++p) acc[r][p] = 0ull;

    for (int jt = 0; jt < NN/32; ++jt) {
        const int j0 = jt * 32;
        __syncthreads();   // previous tile fully consumed

        // ---- load h tile (f32x4 from L2) + per-j factors ----
        const float* hb = g_h + ((size_t)b * NN + j0) * FF;
        #pragma unroll
        for (int v = tid; v < 32*32; v += 128) {
            int j = v >> 5, c4 = v & 31;
            ((float4*)sh_h[j])[c4] = ((const float4*)(hb + (size_t)j * FF))[c4];
        }
        if (tid < 32) {
            float4 d = g_duv[b * NN + j0 + tid];
            sh_dst[tid] = d.x; sh_U[tid] = d.y; sh_V[tid] = d.z;
        }
        __syncthreads();

        // ---- weight phase: thread = (j = tid&31, 8 i's). No exp. ----
        {
            const int j  = tid & 31;
            const int i0 = (tid >> 5) * 8;
            const float dj = sh_dst[j], Uj = sh_U[j], Vj = sh_V[j];
            #pragma unroll
            for (int ii = 0; ii < 8; ++ii) {
                int i = i0 + ii;
                unsigned mw = __ldg(&g_mask[(size_t)(row0 + i) * (NN/32) + jt]);
                float Pi = sh_P[i];
                float e  = sh_src[i] + dj;
                float w  = (e > 0.f) ? Pi * Uj : sh_Q[i] * Vj;
                if (Pi < 0.f) w = rN;                 // isolated row -> uniform
                w = ((mw >> j) & 1u) ? w : 0.f;
                sh_wp[i][j] = pack2(w, w);
            }
        }
        __syncthreads();

        // ---- FMA phase: j in pairs, FFMA2, broadcast LDS ----
        #pragma unroll 8
        for (int jp = 0; jp < 16; ++jp) {
            const int j = jp * 2;
            ulonglong2 ha0 = *(const ulonglong2*)&sh_h[j][f0];
            ulonglong2 ha1 = *(const ulonglong2*)&sh_h[j][f0 + 4];
            ulonglong2 hb0 = *(const ulonglong2*)&sh_h[j + 1][f0];
            ulonglong2 hb1 = *(const ulonglong2*)&sh_h[j + 1][f0 + 4];
            #pragma unroll
            for (int r = 0; r < 4; ++r) {
                ulonglong2 wp = *(const ulonglong2*)&sh_wp[ib + r][j]; // {w_j, w_j+1}
                fma2(acc[r][0], wp.x, ha0.x);
                fma2(acc[r][1], wp.x, ha0.y);
                fma2(acc[r][2], wp.x, ha1.x);
                fma2(acc[r][3], wp.x, ha1.y);
                fma2(acc[r][0], wp.y, hb0.x);
                fma2(acc[r][1], wp.y, hb0.y);
                fma2(acc[r][2], wp.y, hb1.x);
                fma2(acc[r][3], wp.y, hb1.y);
            }
        }
    }

    // ---- epilogue: ELU + store ----
    #pragma unroll
    for (int r = 0; r < 4; ++r) {
        int row = row0 + ib + r;
        float2 p0 = unpack2(acc[r][0]);
        float2 p1 = unpack2(acc[r][1]);
        float2 p2 = unpack2(acc[r][2]);
        float2 p3 = unpack2(acc[r][3]);
        float v[8] = {p0.x, p0.y, p1.x, p1.y, p2.x, p2.y, p3.x, p3.y};
        #pragma unroll
        for (int q = 0; q < 8; ++q)
            v[q] = v[q] > 0.f ? v[q] : (__expf(v[q]) - 1.0f);   // ELU
        *(float4*)&out[(size_t)row * FF + f0]     = make_float4(v[0], v[1], v[2], v[3]);
        *(float4*)&out[(size_t)row * FF + f0 + 4] = make_float4(v[4], v[5], v[6], v[7]);
    }
}

// ===========================================================================
extern "C" void kernel_launch(void* const* d_in, const int* in_sizes, int n_in,
                              void* d_out, int out_size) {
    const float* input = (const float*)d_in[0];   // [8,2048,128] f32
    const int*   adj   = (const int*)  d_in[1];   // [8,2048,2048] i32
    const float* W     = (const float*)d_in[2];   // [128,128] f32
    const float* a_src = (const float*)d_in[3];   // [128,1] f32
    const float* a_dst = (const float*)d_in[4];   // [128,1] f32
    float* out = (float*)d_out;                   // [8,2048,128] f32

    k1_gemm<<<ROWS/64, 256>>>(input, W);
    k1b_proj<<<ROWS/8, 256>>>(a_src, a_dst);
    k2_stats<<<ROWS/8, 256>>>(adj);
    k3_agg<<<ROWS/32, 128>>>(out);
}